// round 1
// baseline (speedup 1.0000x reference)
#include <cuda_runtime.h>
#include <cstdint>

// Problem constants
#define BSZ 32
#define CIN 1024
#define P1  256
#define P3  1024
#define HH  28
#define WW  28
#define HWP 784      // 28*28

// ---------------- scratch (device globals; no allocation allowed) ----------
__device__ float d_y1 [BSZ * P1 * HWP];   // conv1 output (pre-shuffle)
__device__ float d_y1s[BSZ * P1 * HWP];   // shuffled conv1 output
__device__ float d_y2 [BSZ * P1 * HWP];   // 3x3 conv output
__device__ float d_w1t[CIN * P1];         // w1 transposed:  [k=cin][m=oc]
__device__ float d_wdt[9 * P1 * P1];      // wd reordered:   [t][c][oc], k = t*256+c
__device__ float d_w3t[P1 * P3];          // w3 transposed:  [k=c][m=oc]

// ---------------- weight prep ----------------------------------------------
__global__ void prep_w1(const float* __restrict__ w1) {
    int i = blockIdx.x * 256 + threadIdx.x;          // w1: [256 oc][1024 cin]
    if (i < P1 * CIN) {
        int m = i / CIN, k = i % CIN;
        d_w1t[k * P1 + m] = w1[i];
    }
}
__global__ void prep_wd(const float* __restrict__ wd) {
    int i = blockIdx.x * 256 + threadIdx.x;          // wd: [256 oc][256 c][3][3]
    if (i < P1 * P1 * 9) {
        int oc = i / (P1 * 9);
        int r  = i % (P1 * 9);
        int c  = r / 9;
        int t  = r % 9;                               // t = ky*3+kx
        d_wdt[(t * P1 + c) * P1 + oc] = wd[i];
    }
}
__global__ void prep_w3(const float* __restrict__ w3) {
    int i = blockIdx.x * 256 + threadIdx.x;          // w3: [1024 oc][256 c]
    if (i < P3 * P1) {
        int oc = i / P1, c = i % P1;
        d_w3t[c * P3 + oc] = w3[i];
    }
}

// ---------------- per-channel spatial shuffle (gather) ----------------------
__global__ void shuffle_dconv(const int* __restrict__ perm) {
    int plane = blockIdx.x;                 // b*256 + c  (8192 planes)
    int c = plane & (P1 - 1);
    const float* in  = d_y1  + (size_t)plane * HWP;
    float*       out = d_y1s + (size_t)plane * HWP;
    const int*   p   = perm + c * HWP;
    for (int j = threadIdx.x; j < HWP; j += 256)
        out[j] = in[p[j]];
}

// ---------------- tiled SGEMM (128x128x8, 256 thr, 8x8 microtile) -----------
// MODE 0: conv1   C = relu(w1t^T-ish GEMM over x),          M=256,  K=1024
// MODE 1: dconv   implicit 3x3 GEMM over shuffled y1,       M=256,  K=2304 (t-major)
// MODE 2: conv3   GEMM over y2 + shuffled residual + relu,  M=1024, K=256
template <int MODE>
__global__ void __launch_bounds__(256)
gemm_k(const float* __restrict__ Bx,      // MODE 0: x
       float* __restrict__ Outx,          // MODE 2: final out
       const float* __restrict__ Res,     // MODE 2: x (residual)
       const int* __restrict__ Perm)      // MODE 2: perm_res
{
    constexpr int M  = (MODE == 2) ? 1024 : 256;
    constexpr int K  = (MODE == 0) ? 1024 : (MODE == 1 ? 2304 : 256);
    constexpr int CB = (MODE == 1) ? 256 : K;        // batch channel-stride of B

    const float* A     = (MODE == 0) ? d_w1t : (MODE == 1 ? d_wdt : d_w3t);
    const float* Bglob = (MODE == 0) ? Bx    : (MODE == 1 ? d_y1s : d_y2);
    float*       Out   = (MODE == 2) ? Outx  : (MODE == 0 ? d_y1 : d_y2);

    const int b  = blockIdx.z;
    const int m0 = blockIdx.y * 128;
    const int n0 = blockIdx.x * 128;
    const int tid = threadIdx.x;
    const int ty = tid >> 4;    // 0..15 -> 8 rows each
    const int tx = tid & 15;    // 0..15 -> 8 cols each

    const float* Bb = Bglob + (size_t)b * CB * HWP;

    __shared__ float As[8][128];
    __shared__ float Bs[8][128];

    float acc[8][8];
    #pragma unroll
    for (int i = 0; i < 8; i++)
        #pragma unroll
        for (int j = 0; j < 8; j++) acc[i][j] = 0.0f;

    for (int k0 = 0; k0 < K; k0 += 8) {
        // ---- load A tile: [8 k][128 m], coalesced (A is k-major) ----
        #pragma unroll
        for (int i = 0; i < 4; i++) {
            int idx = tid + i * 256;
            int kl = idx >> 7, ml = idx & 127;
            As[kl][ml] = A[(size_t)(k0 + kl) * M + (m0 + ml)];
        }
        // ---- load B tile: [8 k][128 n] ----
        #pragma unroll
        for (int i = 0; i < 4; i++) {
            int idx = tid + i * 256;
            int kl = idx >> 7, jl = idx & 127;
            int k  = k0 + kl;
            int j  = n0 + jl;
            float v = 0.0f;
            if (MODE == 1) {
                // k = t*256 + c ; tap t = ky*3+kx, shifted gather with pad=1 mask
                int t = k >> 8, c = k & 255;
                int dy = t / 3 - 1, dx = t - (t / 3) * 3 - 1;
                if (j < HWP) {
                    int h = j / WW, w = j - h * WW;
                    int hh = h + dy, ww = w + dx;
                    if ((unsigned)hh < HH && (unsigned)ww < WW)
                        v = Bb[c * HWP + hh * WW + ww];
                }
            } else {
                if (j < HWP) v = Bb[(size_t)k * HWP + j];
            }
            Bs[kl][jl] = v;
        }
        __syncthreads();

        #pragma unroll
        for (int kk = 0; kk < 8; kk++) {
            float a[8], bb[8];
            #pragma unroll
            for (int i = 0; i < 8; i++) a[i] = As[kk][ty * 8 + i];
            #pragma unroll
            for (int j = 0; j < 8; j++) bb[j] = Bs[kk][tx * 8 + j];
            #pragma unroll
            for (int i = 0; i < 8; i++)
                #pragma unroll
                for (int j = 0; j < 8; j++)
                    acc[i][j] = fmaf(a[i], bb[j], acc[i][j]);
        }
        __syncthreads();
    }

    // ---- epilogue ----
    #pragma unroll
    for (int i = 0; i < 8; i++) {
        int m = m0 + ty * 8 + i;
        #pragma unroll
        for (int j = 0; j < 8; j++) {
            int n = n0 + tx * 8 + j;
            if (n < HWP) {
                float v = acc[i][j];
                if (MODE == 2) {
                    int p = Perm[m * HWP + n];
                    v += Res[((size_t)b * CIN + m) * HWP + p];
                }
                v = fmaxf(v, 0.0f);
                Out[((size_t)b * M + m) * HWP + n] = v;
            }
        }
    }
}

// ---------------- launch ----------------------------------------------------
extern "C" void kernel_launch(void* const* d_in, const int* in_sizes, int n_in,
                              void* d_out, int out_size)
{
    const float* x  = (const float*)d_in[0];
    const float* w1 = (const float*)d_in[1];
    const float* wd = (const float*)d_in[2];
    const float* w3 = (const float*)d_in[3];
    const int*   pd = (const int*)d_in[4];
    const int*   pr = (const int*)d_in[5];
    float* out = (float*)d_out;

    // weight prep (cheap, deterministic each call)
    prep_w1<<<(P1 * CIN + 255) / 256, 256>>>(w1);
    prep_wd<<<(P1 * P1 * 9 + 255) / 256, 256>>>(wd);
    prep_w3<<<(P3 * P1 + 255) / 256, 256>>>(w3);

    dim3 blk(256);
    dim3 g1((HWP + 127) / 128, P1 / 128, BSZ);    // (7, 2, 32)
    dim3 g3((HWP + 127) / 128, P3 / 128, BSZ);    // (7, 8, 32)

    // conv1 (1x1) + relu
    gemm_k<0><<<g1, blk>>>(x, nullptr, nullptr, nullptr);
    // per-channel spatial shuffle of y1
    shuffle_dconv<<<BSZ * P1, 256>>>(pd);
    // 3x3 conv (pad=1) + relu, implicit GEMM
    gemm_k<1><<<g1, blk>>>(nullptr, nullptr, nullptr, nullptr);
    // conv3 (1x1) + shuffled residual + relu -> out
    gemm_k<2><<<g3, blk>>>(nullptr, out, x, pr);
}

// round 4
// speedup vs baseline: 6.3662x; 6.3662x over previous
#include <cuda_runtime.h>
#include <cstdint>

#define BSZ 32
#define CIN 1024
#define P1  256
#define P3  1024
#define HH  28
#define WW  28
#define HWP 784

// ---------------- scratch (device globals; no allocation allowed) ----------
__device__ float d_y1 [BSZ * P1 * HWP];   // conv1 output (pre-shuffle)
__device__ float d_y1s[BSZ * P1 * HWP];   // shuffled conv1 output
__device__ float d_y2 [BSZ * P1 * HWP];   // 3x3 conv output
__device__ float d_w1r[P1 * CIN];         // w1, tf32-rounded, [oc][cin]
__device__ float d_wd2[P1 * 9 * P1];      // wd reordered [oc][t*256+c], tf32-rounded
__device__ float d_w3r[P3 * P1];          // w3, tf32-rounded, [oc][c]

// ---------------- helpers ----------------------------------------------------
__device__ __forceinline__ float to_tf32(float x) {
    uint32_t r; asm("cvt.rna.tf32.f32 %0, %1;" : "=r"(r) : "f"(x));
    return __uint_as_float(r);
}
__device__ __forceinline__ uint32_t s2u(const void* p) {
    uint32_t a;
    asm("{ .reg .u64 t; cvta.to.shared.u64 t, %1; cvt.u32.u64 %0, t; }" : "=r"(a) : "l"(p));
    return a;
}
#define SW128(o) ((o) ^ (((o) >> 3) & 0x70))

__device__ __forceinline__ void cpa16(uint32_t dst, const void* src) {
    asm volatile("cp.async.cg.shared.global [%0], [%1], 16;" :: "r"(dst), "l"(src));
}
__device__ __forceinline__ void cpa4(uint32_t dst, const void* src, int sz) {
    asm volatile("cp.async.ca.shared.global [%0], [%1], 4, %2;"
                 :: "r"(dst), "l"(src), "r"(sz));
}
__device__ __forceinline__ void cp_commit() {
    asm volatile("cp.async.commit_group;" ::: "memory");
}
template <int N>
__device__ __forceinline__ void cp_wait() {
    asm volatile("cp.async.wait_group %0;" :: "n"(N) : "memory");
}
__device__ __forceinline__ void ldm_x4(uint32_t* r, uint32_t a) {
    asm volatile("ldmatrix.sync.aligned.m8n8.x4.shared.b16 {%0,%1,%2,%3}, [%4];"
        : "=r"(r[0]), "=r"(r[1]), "=r"(r[2]), "=r"(r[3]) : "r"(a));
}
__device__ __forceinline__ void ldm_x2(uint32_t* r, uint32_t a) {
    asm volatile("ldmatrix.sync.aligned.m8n8.x2.shared.b16 {%0,%1}, [%2];"
        : "=r"(r[0]), "=r"(r[1]) : "r"(a));
}
__device__ __forceinline__ void mma8(float* c, const uint32_t* a, const uint32_t* b) {
    asm volatile(
        "mma.sync.aligned.m16n8k8.row.col.f32.tf32.tf32.f32 "
        "{%0,%1,%2,%3}, {%4,%5,%6,%7}, {%8,%9}, {%0,%1,%2,%3};"
        : "+f"(c[0]), "+f"(c[1]), "+f"(c[2]), "+f"(c[3])
        : "r"(a[0]), "r"(a[1]), "r"(a[2]), "r"(a[3]), "r"(b[0]), "r"(b[1]));
}

// ---------------- weight prep ------------------------------------------------
__global__ void prep_w1(const float* __restrict__ w1) {
    int i = blockIdx.x * 256 + threadIdx.x;
    if (i < P1 * CIN) d_w1r[i] = to_tf32(w1[i]);
}
__global__ void prep_wd(const float* __restrict__ wd) {
    int i = blockIdx.x * 256 + threadIdx.x;     // [oc][c][3][3] -> [oc][t*256+c]
    if (i < P1 * P1 * 9) {
        int oc = i / (P1 * 9);
        int r  = i % (P1 * 9);
        int c  = r / 9;
        int t  = r % 9;
        d_wd2[oc * (9 * P1) + t * P1 + c] = to_tf32(wd[i]);
    }
}
__global__ void prep_w3(const float* __restrict__ w3) {
    int i = blockIdx.x * 256 + threadIdx.x;
    if (i < P3 * P1) d_w3r[i] = to_tf32(w3[i]);
}

// ---------------- per-channel spatial shuffle --------------------------------
__global__ void shuffle_dconv(const int* __restrict__ perm) {
    int plane = blockIdx.x;                 // b*256 + c
    int c = plane & (P1 - 1);
    const float* in  = d_y1  + (size_t)plane * HWP;
    float*       out = d_y1s + (size_t)plane * HWP;
    const int*   p   = perm + c * HWP;
    for (int j = threadIdx.x; j < HWP; j += 256)
        out[j] = in[p[j]];
}

// ---------------- TF32 mma.sync GEMM -----------------------------------------
// CTA tile M=128, N=112; K-chunks of 32; cp.async double buffer.
// SMEM per stage: A [128 m][32 k] (16KB) + B [112 n][32 k] (14KB), SW128 rows.
// 8 warps: warp (wm 0..3, wn 0..1) -> 32m x 56n = 2 x 7 m16n8k8 fragments.
// MODE 0: conv1  B=x,   M=256,  K=1024 -> relu -> d_y1
// MODE 1: dconv  B=y1s implicit 3x3,    K=2304 -> relu -> d_y2
// MODE 2: conv3  B=y2,  M=1024, K=256  -> relu(acc + res gather) -> out
template <int MODE>
__global__ void __launch_bounds__(256)
mma_gemm(const float* __restrict__ Bx, float* __restrict__ Outx,
         const float* __restrict__ Res, const int* __restrict__ Perm)
{
    constexpr int M   = (MODE == 2) ? P3 : P1;
    constexpr int K   = (MODE == 0) ? CIN : (MODE == 1 ? 2304 : P1);
    constexpr int NCH = K / 32;
    constexpr int CB  = (MODE == 1) ? P1 : K;
    constexpr uint32_t STG = 30720u;        // 16KB A + 14KB B per stage

    const float* A  = (MODE == 0) ? d_w1r : (MODE == 1 ? d_wd2 : d_w3r);
    const float* Bg = (MODE == 0) ? Bx    : (MODE == 1 ? d_y1s : d_y2);
    float*       Out = (MODE == 2) ? Outx : (MODE == 0 ? d_y1 : d_y2);

    const int b   = blockIdx.z;
    const int m0  = blockIdx.y * 128;
    const int n0  = blockIdx.x * 112;
    const int tid = threadIdx.x;
    const int wid = tid >> 5;
    const int lid = tid & 31;
    const int wm  = wid & 3;
    const int wn  = wid >> 2;

    extern __shared__ char smem[];
    const uint32_t sb = (s2u(smem) + 1023u) & ~1023u;

    const float* Bb  = Bg + (size_t)b * CB * HWP;
    const float* Ag0 = A + (size_t)m0 * K;

    // ldmatrix per-lane row byte-offsets (before swizzle)
    const uint32_t roA  = (uint32_t)((wm * 32 + (lid & 15)) * 128 + (lid >> 4) * 16);
    const uint32_t roB4 = (uint32_t)((wn * 56 + (lid >> 4) * 8 + (lid & 7)) * 128 +
                                     ((lid >> 3) & 1) * 16);
    const uint32_t roB2 = (uint32_t)((wn * 56 + 48 + (lid & 7)) * 128 +
                                     ((lid >> 3) & 1) * 16);

    float acc[2][7][4];
    #pragma unroll
    for (int i = 0; i < 2; i++)
        #pragma unroll
        for (int j = 0; j < 7; j++)
            #pragma unroll
            for (int q = 0; q < 4; q++) acc[i][j][q] = 0.0f;

    auto load_chunk = [&](int st, int ch) {
        const uint32_t As = sb + (uint32_t)st * STG;
        const uint32_t Bs = As + 16384u;
        const int k0 = ch * 32;
        // A tile: 1024 float4
        const float* Ag = Ag0 + k0;
        #pragma unroll
        for (int i = 0; i < 4; i++) {
            int idx = tid + i * 256;
            int r = idx >> 3, q = idx & 7;
            cpa16(As + SW128((uint32_t)(r * 128 + q * 16)), Ag + (size_t)r * K + q * 4);
        }
        // B tile: 3584 scalars, transposed into [n][k] rows
        if (MODE == 1) {
            const int t  = k0 >> 8;
            const int dy = t / 3 - 1, dx = t - (t / 3) * 3 - 1;
            const int cb = k0 & 255;
            #pragma unroll
            for (int i = 0; i < 14; i++) {
                int idx = tid + i * 256;
                int k = idx / 112, nl = idx - k * 112;
                int n = n0 + nl;
                int h = n / WW, w = n - h * WW;
                int hh = h + dy, ww = w + dx;
                bool ok = ((unsigned)hh < (unsigned)HH) && ((unsigned)ww < (unsigned)WW);
                const float* src = ok ? (Bb + (size_t)(cb + k) * HWP + hh * WW + ww) : Bb;
                cpa4(Bs + SW128((uint32_t)(nl * 128 + k * 4)), src, ok ? 4 : 0);
            }
        } else {
            #pragma unroll
            for (int i = 0; i < 14; i++) {
                int idx = tid + i * 256;
                int k = idx / 112, nl = idx - k * 112;
                cpa4(Bs + SW128((uint32_t)(nl * 128 + k * 4)),
                     Bb + (size_t)(k0 + k) * HWP + n0 + nl, 4);
            }
        }
    };

    auto compute = [&](int st) {
        const uint32_t As = sb + (uint32_t)st * STG;
        const uint32_t Bs = As + 16384u;
        #pragma unroll
        for (int s = 0; s < 4; s++) {
            uint32_t af[2][4];
            ldm_x4(af[0], As + SW128(roA + s * 32));
            ldm_x4(af[1], As + SW128(roA + 2048u + s * 32));
            uint32_t bf[7][2];
            #pragma unroll
            for (int j = 0; j < 3; j++) {
                uint32_t r4[4];
                ldm_x4(r4, Bs + SW128(roB4 + (uint32_t)j * 2048u + s * 32));
                bf[2 * j][0] = r4[0]; bf[2 * j][1] = r4[1];
                bf[2 * j + 1][0] = r4[2]; bf[2 * j + 1][1] = r4[3];
            }
            ldm_x2(bf[6], Bs + SW128(roB2 + s * 32));
            #pragma unroll
            for (int mi = 0; mi < 2; mi++)
                #pragma unroll
                for (int ni = 0; ni < 7; ni++)
                    mma8(acc[mi][ni], af[mi], bf[ni]);
        }
    };

    // ---- pipelined mainloop ----
    load_chunk(0, 0);
    cp_commit();
    for (int ch = 0; ch < NCH; ch++) {
        if (ch + 1 < NCH) {
            load_chunk((ch + 1) & 1, ch + 1);
            cp_commit();
            cp_wait<1>();
        } else {
            cp_wait<0>();
        }
        __syncthreads();
        compute(ch & 1);
        __syncthreads();
    }

    // ---- epilogue ----
    const int gid = lid >> 2, tig = lid & 3;
    #pragma unroll
    for (int mi = 0; mi < 2; mi++) {
        const int m = m0 + wm * 32 + mi * 16 + gid;
        float* row0 = Out + ((size_t)b * M + m) * HWP + n0 + wn * 56;
        float* row1 = row0 + 8 * HWP;
        const float* rr0 = nullptr; const float* rr1 = nullptr;
        const int* pp0 = nullptr; const int* pp1 = nullptr;
        if (MODE == 2) {
            rr0 = Res + ((size_t)b * CIN + m) * HWP;
            rr1 = rr0 + 8 * HWP;
            pp0 = Perm + (size_t)m * HWP;
            pp1 = pp0 + 8 * HWP;
        }
        #pragma unroll
        for (int ni = 0; ni < 7; ni++) {
            const int noff = ni * 8 + tig * 2;
            float v0 = acc[mi][ni][0], v1 = acc[mi][ni][1];
            float v2 = acc[mi][ni][2], v3 = acc[mi][ni][3];
            if (MODE == 2) {
                const int gn = n0 + wn * 56 + noff;
                v0 += __ldg(rr0 + __ldg(pp0 + gn));
                v1 += __ldg(rr0 + __ldg(pp0 + gn + 1));
                v2 += __ldg(rr1 + __ldg(pp1 + gn));
                v3 += __ldg(rr1 + __ldg(pp1 + gn + 1));
            }
            *(float2*)(row0 + noff) = make_float2(fmaxf(v0, 0.f), fmaxf(v1, 0.f));
            *(float2*)(row1 + noff) = make_float2(fmaxf(v2, 0.f), fmaxf(v3, 0.f));
        }
    }
}

// ---------------- launch ----------------------------------------------------
extern "C" void kernel_launch(void* const* d_in, const int* in_sizes, int n_in,
                              void* d_out, int out_size)
{
    const float* x  = (const float*)d_in[0];
    const float* w1 = (const float*)d_in[1];
    const float* wd = (const float*)d_in[2];
    const float* w3 = (const float*)d_in[3];
    const int*   pd = (const int*)d_in[4];
    const int*   pr = (const int*)d_in[5];
    float* out = (float*)d_out;

    const int SMEMB = 2 * 30720 + 1024;

    static bool attr_done = false;
    if (!attr_done) {
        cudaFuncSetAttribute(mma_gemm<0>, cudaFuncAttributeMaxDynamicSharedMemorySize, SMEMB);
        cudaFuncSetAttribute(mma_gemm<1>, cudaFuncAttributeMaxDynamicSharedMemorySize, SMEMB);
        cudaFuncSetAttribute(mma_gemm<2>, cudaFuncAttributeMaxDynamicSharedMemorySize, SMEMB);
        attr_done = true;
    }

    prep_w1<<<(P1 * CIN + 255) / 256, 256>>>(w1);
    prep_wd<<<(P1 * P1 * 9 + 255) / 256, 256>>>(wd);
    prep_w3<<<(P3 * P1 + 255) / 256, 256>>>(w3);

    dim3 blk(256);
    dim3 g1(7, 2, BSZ);
    dim3 g3(7, 8, BSZ);

    mma_gemm<0><<<g1, blk, SMEMB>>>(x, nullptr, nullptr, nullptr);
    shuffle_dconv<<<BSZ * P1, 256>>>(pd);
    mma_gemm<1><<<g1, blk, SMEMB>>>(nullptr, nullptr, nullptr, nullptr);
    mma_gemm<2><<<g3, blk, SMEMB>>>(nullptr, out, x, pr);
}